// round 13
// baseline (speedup 1.0000x reference)
#include <cuda_runtime.h>
#include <cuda_bf16.h>
#include <cstdint>

#define HB 128      // batch
#define HC 64       // states
#define NEG_INF (-3.402823466e38f)
// float32(0.5 * log(2*pi))
#define HALF_LOG2PI 0.91893853320467274178f

// ---------- packed f32x2 helpers (Blackwell) ----------
__device__ __forceinline__ unsigned long long pack2(float lo, float hi) {
    unsigned long long r;
    asm("mov.b64 %0, {%1, %2};" : "=l"(r) : "f"(lo), "f"(hi));
    return r;
}
__device__ __forceinline__ void unpack2(unsigned long long v, float& lo, float& hi) {
    asm("mov.b64 {%0, %1}, %2;" : "=f"(lo), "=f"(hi) : "l"(v));
}
__device__ __forceinline__ unsigned long long fma2(unsigned long long a,
                                                   unsigned long long b,
                                                   unsigned long long c) {
    unsigned long long d;
    asm("fma.rn.f32x2 %0, %1, %2, %3;" : "=l"(d) : "l"(a), "l"(b), "l"(c));
    return d;
}

// predicated mask-bit set: if (a == b) m |= bit
#define SETP_OR(m, a, b, bit)                                              \
    asm("{ .reg .pred p; setp.eq.f32 p, %1, %2; @p or.b32 %0, %0, %3; }"   \
        : "+r"(m) : "f"(a), "f"(b), "r"(bit))

__device__ __forceinline__ float warp_max_bfly(float v) {
    #pragma unroll
    for (int off = 16; off >= 1; off >>= 1)
        v = fmaxf(v, __shfl_xor_sync(0xffffffff, v, off));
    return v;
}

// ---------- fast emission (forward path) ----------
__device__ __forceinline__ float emis_fast(float4 xv, const float* iv,
                                           const float* muiv, float K) {
    float z0 = fmaf(xv.x, iv[0], muiv[0]);
    float z1 = fmaf(xv.y, iv[1], muiv[1]);
    float z2 = fmaf(xv.z, iv[2], muiv[2]);
    float z3 = fmaf(xv.w, iv[3], muiv[3]);
    float qa = fmaf(z0, z0, z1 * z1);
    float qb = fmaf(z2, z2, z3 * z3);
    return fmaf(-0.5f, qa + qb, K);
}

__global__ __launch_bounds__(192, 1)
void MyHMM_14353780703777_kernel(const float* __restrict__ x,
                                 const float* __restrict__ means,
                                 const float* __restrict__ stds,
                                 const float* __restrict__ logA,
                                 const float* __restrict__ logpi,
                                 float* __restrict__ out, int T) {
    extern __shared__ char smem[];
    float4* xs          = (float4*)smem;                       // T * 16 bytes
    float*  abuf        = (float*)(smem + 16 * (size_t)T);     // 2*64 (forward alpha dbl-buf)
    float*  dbuf        = abuf + 128;                          // 2*64 (viterbi d dbl-buf)
    float*  Abuf        = dbuf + 128;                          // 64*65 padded raw logA
    float*  rowmx       = Abuf + 64 * 65;                      // 64 row maxes
    float*  rowls       = rowmx + 64;                          // 64 row lse's
    float*  piaux       = rowls + 64;                          // [0]=pimax, [1]=pilse (pad 16)
    unsigned char* psi  = (unsigned char*)(piaux + 16);        // (T-1)*64 backpointers

    const int b = blockIdx.x;
    const int tid = threadIdx.x;
    const float* xb = x + (size_t)b * T * 6;

    // ---- preload x[b, :, 0:4] as float4 ----
    for (int i = tid; i < T; i += 192) {
        const float* p = xb + i * 6;
        xs[i] = make_float4(p[0], p[1], p[2], p[3]);
    }
    // ---- load raw log_A into padded smem ----
    for (int i = tid; i < HC * HC; i += 192) {
        Abuf[(i >> 6) * 65 + (i & 63)] = logA[i];
    }
    __syncthreads();

    // ---- log_softmax prep (accurate expf/logf, sequential sums -> ref-exact) ----
    if (tid < HC) {
        const int r = tid;
        float mx = NEG_INF;
        #pragma unroll 8
        for (int j = 0; j < HC; j++) mx = fmaxf(mx, Abuf[r * 65 + j]);
        float s = 0.0f;
        #pragma unroll 8
        for (int j = 0; j < HC; j++)
            s = __fadd_rn(s, expf(__fsub_rn(Abuf[r * 65 + j], mx)));
        rowmx[r] = mx;
        rowls[r] = logf(s);
    }
    if (tid == 0) {
        float mx = NEG_INF;
        for (int j = 0; j < HC; j++) mx = fmaxf(mx, logpi[j]);
        float s = 0.0f;
        for (int j = 0; j < HC; j++)
            s = __fadd_rn(s, expf(__fsub_rn(logpi[j], mx)));
        piaux[0] = mx;
        piaux[1] = logf(s);
    }
    __syncthreads();
    const float pimx = piaux[0];
    const float pils = piaux[1];

    if (tid < 32) {
        // ========== FORWARD (1 warp, 2 states/thread, prob-space, deferred renorm,
        //            packed-f32x2 matvec) ==========
        const int c0 = tid, c1 = tid + 32;
        float iv0[4], muiv0[4], iv1[4], muiv1[4];
        float K0 = 0.0f, K1 = 0.0f;
        #pragma unroll
        for (int d = 0; d < 4; d++) {
            float s0 = fmaxf(stds[c0 * 6 + d], 0.0f) + 0.1f;
            float s1 = fmaxf(stds[c1 * 6 + d], 0.0f) + 0.1f;
            iv0[d] = 1.0f / s0;                     iv1[d] = 1.0f / s1;
            muiv0[d] = -means[c0 * 6 + d] * iv0[d]; muiv1[d] = -means[c1 * 6 + d] * iv1[d];
            K0 += -logf(s0) - HALF_LOG2PI;
            K1 += -logf(s1) - HALF_LOG2PI;
        }
        const float pil0 = (logpi[c0] - pimx) - pils;
        const float pil1 = (logpi[c1] - pimx) - pils;

        // transition columns (prob space), packed over j-pairs
        unsigned long long Aep0[32], Aep1[32];
        #pragma unroll
        for (int k = 0; k < 32; k++) {
            int j = 2 * k;
            float a0 = __expf((Abuf[j * 65 + c0] - rowmx[j]) - rowls[j]);
            float b0 = __expf((Abuf[(j + 1) * 65 + c0] - rowmx[j + 1]) - rowls[j + 1]);
            float a1 = __expf((Abuf[j * 65 + c1] - rowmx[j]) - rowls[j]);
            float b1 = __expf((Abuf[(j + 1) * 65 + c1] - rowmx[j + 1]) - rowls[j + 1]);
            Aep0[k] = pack2(a0, b0);
            Aep1[k] = pack2(a1, b1);
        }

        // t = 0
        float4 xv = xs[0];
        float lpA = emis_fast(xv, iv0, muiv0, K0) + pil0;
        float lpB = emis_fast(xv, iv1, muiv1, K1) + pil1;
        float g = warp_max_bfly(fmaxf(lpA, lpB));
        float u0 = __expf(lpA - g);
        float u1 = __expf(lpB - g);
        double acc = (double)g;

        float* aprev = abuf;
        float* acur  = abuf + 64;
        aprev[c0] = u0; aprev[c1] = u1;
        __syncwarp();

        float rprev = 1.0f;           // 1/m_{t-1}
        float lpend = 0.0f;           // log(m_{t-1}) pending
        float w0 = u0, w1 = u1;

        for (int t = 1; t < T; t++) {
            float4 xq = xs[t];
            float l0 = emis_fast(xq, iv0, muiv0, K0);
            float l1 = emis_fast(xq, iv1, muiv1, K1);
            // reduction (MIO) overlaps the matvec (FMA pipe)
            float gt = warp_max_bfly(fmaxf(l0, l1));

            // packed matvec: 64 FFMA2, dual accumulators per state
            unsigned long long v0p = 0, v0q = 0, v1p = 0, v1q = 0;
            #pragma unroll
            for (int j = 0; j < 64; j += 4) {
                ulonglong2 av = *(const ulonglong2*)(aprev + j);
                v0p = fma2(av.x, Aep0[j / 2],     v0p);
                v1p = fma2(av.x, Aep1[j / 2],     v1p);
                v0q = fma2(av.y, Aep0[j / 2 + 1], v0q);
                v1q = fma2(av.y, Aep1[j / 2 + 1], v1q);
            }
            float v0a, v0b, v0c, v0d, v1a, v1b, v1c, v1d;
            unpack2(v0p, v0a, v0b); unpack2(v0q, v0c, v0d);
            unpack2(v1p, v1a, v1b); unpack2(v1q, v1c, v1d);

            float e0 = __expf(l0 - gt) * rprev;
            float e1 = __expf(l1 - gt) * rprev;
            w0 = e0 * ((v0a + v0b) + (v0c + v0d));
            w1 = e1 * ((v1a + v1b) + (v1c + v1d));
            acur[c0] = w0; acur[c1] = w1;       // store BEFORE reduction
            __syncwarp();
            acc += (double)gt + (double)lpend;

            float m = warp_max_bfly(fmaxf(w0, w1));
            rprev = __frcp_rn(m);
            lpend = __logf(m);

            float* tmp = aprev; aprev = acur; acur = tmp;
        }

        // logp_x = acc + log(m_{T-1}) + log(sum of last stored w)
        float s = w0 + w1;
        #pragma unroll
        for (int off = 16; off >= 1; off >>= 1)
            s += __shfl_xor_sync(0xffffffff, s, off);
        if (tid == 0) out[b] = (float)(acc + (double)lpend + (double)__logf(s));

    } else if (tid >= 64) {
        // ========== VITERBI (4 warps, 2 threads/state, j-halves, ref-exact f32) ==========
        const int vt   = tid - 64;     // 0..127
        const int c    = vt >> 1;      // state 0..63
        const int half = vt & 1;       // 0: j in [0,32), dims 0-1 | 1: j in [32,64), dims 2-3
        const int jb   = half * 32;

        float muh[2], sgh[2], lsgh[2];
        #pragma unroll
        for (int k = 0; k < 2; k++) {
            int d = half * 2 + k;
            sgh[k]  = __fadd_rn(fmaxf(stds[c * 6 + d], 0.0f), 0.1f);
            muh[k]  = means[c * 6 + d];
            lsgh[k] = logf(sgh[k]);
        }
        const float pil = __fsub_rn(__fsub_rn(logpi[c], pimx), pils);

        // normalized logA half-column (ref-exact log_softmax values)
        float Al[32];
        #pragma unroll
        for (int j = 0; j < 32; j++)
            Al[j] = __fsub_rn(__fsub_rn(Abuf[(jb + j) * 65 + c], rowmx[jb + j]), rowls[jb + j]);

        float* dprev = dbuf;
        float* dcur  = dbuf + 64;

        // t = 0: split emission, exchange partials, even stores
        {
            float4 xv = xs[0];
            float xa = half ? xv.z : xv.x;
            float xb2 = half ? xv.w : xv.y;
            float z0 = __fdiv_rn(__fsub_rn(xa, muh[0]), sgh[0]);
            float z1 = __fdiv_rn(__fsub_rn(xb2, muh[1]), sgh[1]);
            float eA = __fsub_rn(__fsub_rn(__fmul_rn(__fmul_rn(-0.5f, z0), z0), lsgh[0]), HALF_LOG2PI);
            float eB = __fsub_rn(__fsub_rn(__fmul_rn(__fmul_rn(-0.5f, z1), z1), lsgh[1]), HALF_LOG2PI);
            float e2 = __shfl_down_sync(0xffffffff, eA, 1);
            float e3 = __shfl_down_sync(0xffffffff, eB, 1);
            if (!half) {
                float lp = __fadd_rn(__fadd_rn(__fadd_rn(eA, eB), e2), e3);
                dprev[c] = __fadd_rn(lp, pil);
            }
            asm volatile("bar.sync 1, 128;" ::: "memory");
        }

        for (int t = 1; t < T; t++) {
            float4 xq = xs[t];
            float xa = half ? xq.z : xq.x;
            float xb2 = half ? xq.w : xq.y;
            float z0 = __fdiv_rn(__fsub_rn(xa, muh[0]), sgh[0]);
            float z1 = __fdiv_rn(__fsub_rn(xb2, muh[1]), sgh[1]);
            float eA = __fsub_rn(__fsub_rn(__fmul_rn(__fmul_rn(-0.5f, z0), z0), lsgh[0]), HALF_LOG2PI);
            float eB = __fsub_rn(__fsub_rn(__fmul_rn(__fmul_rn(-0.5f, z1), z1), lsgh[1]), HALF_LOG2PI);

            // half-lattice: 32 order-exact adds
            float v[32];
            #pragma unroll
            for (int j = 0; j < 32; j += 4) {
                float4 dv = *(const float4*)(dprev + jb + j);
                v[j]     = __fadd_rn(dv.x, Al[j]);
                v[j + 1] = __fadd_rn(dv.y, Al[j + 1]);
                v[j + 2] = __fadd_rn(dv.z, Al[j + 2]);
                v[j + 3] = __fadd_rn(dv.w, Al[j + 3]);
            }
            // half max tree (exact, order-free)
            float m16[16];
            #pragma unroll
            for (int j = 0; j < 16; j++) m16[j] = fmaxf(v[2 * j], v[2 * j + 1]);
            float m8[8];
            #pragma unroll
            for (int j = 0; j < 8; j++) m8[j] = fmaxf(m16[2 * j], m16[2 * j + 1]);
            float m4[4];
            #pragma unroll
            for (int j = 0; j < 4; j++) m4[j] = fmaxf(m8[2 * j], m8[2 * j + 1]);
            float bh = fmaxf(fmaxf(m4[0], m4[1]), fmaxf(m4[2], m4[3]));

            // pair exchange (odd -> even): half1 best + emission partials
            float b1 = __shfl_down_sync(0xffffffff, bh, 1);
            float e2 = __shfl_down_sync(0xffffffff, eA, 1);
            float e3 = __shfl_down_sync(0xffffffff, eB, 1);

            if (!half) {
                float best = fmaxf(bh, b1);
                float lp = __fadd_rn(__fadd_rn(__fadd_rn(eA, eB), e2), e3);
                dcur[c] = __fadd_rn(__fadd_rn(best, lp) - lp + lp, 0.0f) ; // placeholder removed below
                dcur[c] = __fadd_rn(best, lp);
            }
            asm volatile("bar.sync 1, 128;" ::: "memory");

            // post-barrier: argmax mask (off the recurrence path; feeds psi only)
            unsigned mk = 0;
            #pragma unroll
            for (int g = 0; g < 4; g++) {
                unsigned m = 0;
                #pragma unroll
                for (int k = 0; k < 8; k++) {
                    unsigned bit = 1u << (g * 8 + k);
                    SETP_OR(m, v[g * 8 + k], bh, bit);
                }
                mk |= m;
            }
            unsigned mk1 = __shfl_down_sync(0xffffffff, mk, 1);
            if (!half) {
                // first-max: half0 wins ties (lower index), lowest set bit within half
                int bi = (bh >= b1) ? (__ffs(mk) - 1) : (__ffs(mk1) + 31);
                psi[(t - 1) * 64 + c] = (unsigned char)bi;
            }
            float* tmp = dprev; dprev = dcur; dcur = tmp;
        }
        // ensure all psi stores (issued post-barrier) are visible before backtrack
        asm volatile("bar.sync 1, 128;" ::: "memory");

        // backtrack (single thread; psi in smem -> LDS-latency chase)
        if (vt == 0) {
            float bb = dprev[0]; int cl = 0;
            #pragma unroll 8
            for (int j = 1; j < 64; j++) {
                float vv = dprev[j];
                if (vv > bb) { bb = vv; cl = j; }
            }
            float* oc = out + HB + (size_t)b * T;
            int cc = cl;
            oc[T - 1] = (float)cc;
            for (int t = T - 2; t >= 0; --t) {
                cc = psi[t * 64 + cc];
                oc[t] = (float)cc;
            }
        }
    }
    // tid 32..63: idle warp (never touches named barrier 1)
}

extern "C" void kernel_launch(void* const* d_in, const int* in_sizes, int n_in,
                              void* d_out, int out_size) {
    const float* x      = (const float*)d_in[0];
    const float* means  = (const float*)d_in[1];
    const float* stds   = (const float*)d_in[2];
    const float* logA   = (const float*)d_in[3];
    const float* logpi  = (const float*)d_in[4];
    float* out = (float*)d_out;

    int T = in_sizes[0] / (HB * 6);   // 2050

    size_t smem = 16 * (size_t)T          // xs
                + 128 * sizeof(float)     // abuf
                + 128 * sizeof(float)     // dbuf
                + 64 * 65 * sizeof(float) // Abuf (padded)
                + (64 + 64 + 16) * sizeof(float) // rowmx, rowls, piaux
                + (size_t)(T - 1) * 64;   // psi

    cudaFuncSetAttribute(MyHMM_14353780703777_kernel,
                         cudaFuncAttributeMaxDynamicSharedMemorySize, (int)smem);
    MyHMM_14353780703777_kernel<<<HB, 192, smem>>>(x, means, stds, logA, logpi, out, T);
}

// round 14
// speedup vs baseline: 1.4540x; 1.4540x over previous
#include <cuda_runtime.h>
#include <cuda_bf16.h>
#include <cstdint>

#define HB 128      // batch
#define HC 64       // states
#define NEG_INF (-3.402823466e38f)
// float32(0.5 * log(2*pi))
#define HALF_LOG2PI 0.91893853320467274178f

__device__ __forceinline__ float warp_max_bfly(float v) {
    #pragma unroll
    for (int off = 16; off >= 1; off >>= 1)
        v = fmaxf(v, __shfl_xor_sync(0xffffffff, v, off));
    return v;
}

// ---------- ref-exact emission (matches XLA f32 op sequence) ----------
__device__ __forceinline__ float emis_ref(float4 xv, const float* mu,
                                          const float* sg, const float* lsg) {
    float z0 = __fdiv_rn(__fsub_rn(xv.x, mu[0]), sg[0]);
    float z1 = __fdiv_rn(__fsub_rn(xv.y, mu[1]), sg[1]);
    float z2 = __fdiv_rn(__fsub_rn(xv.z, mu[2]), sg[2]);
    float z3 = __fdiv_rn(__fsub_rn(xv.w, mu[3]), sg[3]);
    float e0 = __fsub_rn(__fsub_rn(__fmul_rn(__fmul_rn(-0.5f, z0), z0), lsg[0]), HALF_LOG2PI);
    float e1 = __fsub_rn(__fsub_rn(__fmul_rn(__fmul_rn(-0.5f, z1), z1), lsg[1]), HALF_LOG2PI);
    float e2 = __fsub_rn(__fsub_rn(__fmul_rn(__fmul_rn(-0.5f, z2), z2), lsg[2]), HALF_LOG2PI);
    float e3 = __fsub_rn(__fsub_rn(__fmul_rn(__fmul_rn(-0.5f, z3), z3), lsg[3]), HALF_LOG2PI);
    return __fadd_rn(__fadd_rn(__fadd_rn(e0, e1), e2), e3);
}

// ---------- fast emission (forward path) ----------
__device__ __forceinline__ float emis_fast(float4 xv, const float* iv,
                                           const float* muiv, float K) {
    float z0 = fmaf(xv.x, iv[0], muiv[0]);
    float z1 = fmaf(xv.y, iv[1], muiv[1]);
    float z2 = fmaf(xv.z, iv[2], muiv[2]);
    float z3 = fmaf(xv.w, iv[3], muiv[3]);
    float qa = fmaf(z0, z0, z1 * z1);
    float qb = fmaf(z2, z2, z3 * z3);
    return fmaf(-0.5f, qa + qb, K);
}

__global__ __launch_bounds__(128, 1)
void MyHMM_14353780703777_kernel(const float* __restrict__ x,
                                 const float* __restrict__ means,
                                 const float* __restrict__ stds,
                                 const float* __restrict__ logA,
                                 const float* __restrict__ logpi,
                                 float* __restrict__ out, int T) {
    extern __shared__ char smem[];
    float4* xs          = (float4*)smem;                       // T * 16 bytes
    float*  abuf        = (float*)(smem + 16 * (size_t)T);     // 2*64 (forward alpha dbl-buf)
    float*  dbuf        = abuf + 128;                          // 2*64 (viterbi d dbl-buf)
    float*  lps         = dbuf + 128;                          // 2*64 (emission dbl-buf, viterbi)
    float*  Abuf        = lps + 128;                           // 64*65 padded raw logA
    float*  rowmx       = Abuf + 64 * 65;                      // 64 row maxes
    float*  rowls       = rowmx + 64;                          // 64 row lse's
    float*  piaux       = rowls + 64;                          // [0]=pimax, [1]=pilse (pad 16)
    unsigned char* psi  = (unsigned char*)(piaux + 16);        // (T-1)*64 backpointers

    const int b = blockIdx.x;
    const int tid = threadIdx.x;
    const float* xb = x + (size_t)b * T * 6;

    // ---- preload x[b, :, 0:4] as float4 ----
    for (int i = tid; i < T; i += 128) {
        const float* p = xb + i * 6;
        xs[i] = make_float4(p[0], p[1], p[2], p[3]);
    }
    // ---- load raw log_A into padded smem ----
    for (int i = tid; i < HC * HC; i += 128) {
        Abuf[(i >> 6) * 65 + (i & 63)] = logA[i];
    }
    __syncthreads();

    // ---- log_softmax prep (accurate expf/logf, sequential sums -> ref-exact) ----
    if (tid < HC) {
        const int r = tid;
        float mx = NEG_INF;
        #pragma unroll 8
        for (int j = 0; j < HC; j++) mx = fmaxf(mx, Abuf[r * 65 + j]);
        float s = 0.0f;
        #pragma unroll 8
        for (int j = 0; j < HC; j++)
            s = __fadd_rn(s, expf(__fsub_rn(Abuf[r * 65 + j], mx)));
        rowmx[r] = mx;
        rowls[r] = logf(s);
    }
    if (tid == 0) {
        float mx = NEG_INF;
        for (int j = 0; j < HC; j++) mx = fmaxf(mx, logpi[j]);
        float s = 0.0f;
        for (int j = 0; j < HC; j++)
            s = __fadd_rn(s, expf(__fsub_rn(logpi[j], mx)));
        piaux[0] = mx;
        piaux[1] = logf(s);
    }
    __syncthreads();
    const float pimx = piaux[0];
    const float pils = piaux[1];

    if (tid < 32) {
        // ========== FORWARD (1 warp, 2 states/thread, prob-space, deferred renorm) ==========
        const int c0 = tid, c1 = tid + 32;
        float iv0[4], muiv0[4], iv1[4], muiv1[4];
        float K0 = 0.0f, K1 = 0.0f;
        #pragma unroll
        for (int d = 0; d < 4; d++) {
            float s0 = fmaxf(stds[c0 * 6 + d], 0.0f) + 0.1f;
            float s1 = fmaxf(stds[c1 * 6 + d], 0.0f) + 0.1f;
            iv0[d] = 1.0f / s0;                     iv1[d] = 1.0f / s1;
            muiv0[d] = -means[c0 * 6 + d] * iv0[d]; muiv1[d] = -means[c1 * 6 + d] * iv1[d];
            K0 += -logf(s0) - HALF_LOG2PI;
            K1 += -logf(s1) - HALF_LOG2PI;
        }
        const float pil0 = (logpi[c0] - pimx) - pils;
        const float pil1 = (logpi[c1] - pimx) - pils;

        // register-resident transition columns (prob space)
        float Ae0[64], Ae1[64];
        #pragma unroll
        for (int j = 0; j < 64; j++) {
            Ae0[j] = __expf((Abuf[j * 65 + c0] - rowmx[j]) - rowls[j]);
            Ae1[j] = __expf((Abuf[j * 65 + c1] - rowmx[j]) - rowls[j]);
        }

        // t = 0
        float4 xv = xs[0];
        float lpA = emis_fast(xv, iv0, muiv0, K0) + pil0;
        float lpB = emis_fast(xv, iv1, muiv1, K1) + pil1;
        float g = warp_max_bfly(fmaxf(lpA, lpB));
        float u0 = __expf(lpA - g);
        float u1 = __expf(lpB - g);
        float acc = g;                // f32 accumulator (error ~2e-6 rel, fine)

        float* aprev = abuf;
        float* acur  = abuf + 64;
        aprev[c0] = u0; aprev[c1] = u1;
        __syncwarp();

        float rprev = 1.0f;           // 1/m_{t-1}
        float lpend = 0.0f;           // log(m_{t-1}) pending
        float w0 = u0, w1 = u1;

        for (int t = 1; t < T; t++) {
            float4 xq = xs[t];
            float l0 = emis_fast(xq, iv0, muiv0, K0);
            float l1 = emis_fast(xq, iv1, muiv1, K1);
            // reduction (MIO) overlaps the matvec (FMA pipe)
            float gt = warp_max_bfly(fmaxf(l0, l1));

            float v0a = 0.0f, v0b = 0.0f, v1a = 0.0f, v1b = 0.0f;
            #pragma unroll
            for (int j = 0; j < 64; j += 4) {
                float4 a = *(const float4*)(aprev + j);
                v0a = fmaf(a.x, Ae0[j],     v0a);
                v1a = fmaf(a.x, Ae1[j],     v1a);
                v0b = fmaf(a.y, Ae0[j + 1], v0b);
                v1b = fmaf(a.y, Ae1[j + 1], v1b);
                v0a = fmaf(a.z, Ae0[j + 2], v0a);
                v1a = fmaf(a.z, Ae1[j + 2], v1a);
                v0b = fmaf(a.w, Ae0[j + 3], v0b);
                v1b = fmaf(a.w, Ae1[j + 3], v1b);
            }
            float e0 = __expf(l0 - gt) * rprev;
            float e1 = __expf(l1 - gt) * rprev;
            w0 = e0 * (v0a + v0b);
            w1 = e1 * (v1a + v1b);
            acur[c0] = w0; acur[c1] = w1;       // store BEFORE reduction
            __syncwarp();
            acc += gt + lpend;

            float m = warp_max_bfly(fmaxf(w0, w1));
            rprev = __frcp_rn(m);
            lpend = __logf(m);

            float* tmp = aprev; aprev = acur; acur = tmp;
        }

        // logp_x = acc + log(m_{T-1}) + log(sum of last stored w)
        float s = w0 + w1;
        #pragma unroll
        for (int off = 16; off >= 1; off >>= 1)
            s += __shfl_xor_sync(0xffffffff, s, off);
        if (tid == 0) out[b] = acc + lpend + __logf(s);

    } else if (tid < 64) {
        // ========== EMISSION PRODUCER (1 warp, 2 states/thread, ref-exact) ==========
        // Computes logp[t+1][c] one step ahead into lps[(t+1)&1], synced with the
        // viterbi warps' per-step named barrier (96 threads: warps 1,2,3).
        const int l = tid - 32;
        const int c0 = l, c1 = l + 32;
        float mu0[4], sg0[4], lsg0[4], mu1[4], sg1[4], lsg1[4];
        #pragma unroll
        for (int d = 0; d < 4; d++) {
            sg0[d]  = __fadd_rn(fmaxf(stds[c0 * 6 + d], 0.0f), 0.1f);
            sg1[d]  = __fadd_rn(fmaxf(stds[c1 * 6 + d], 0.0f), 0.1f);
            mu0[d]  = means[c0 * 6 + d];
            mu1[d]  = means[c1 * 6 + d];
            lsg0[d] = logf(sg0[d]);
            lsg1[d] = logf(sg1[d]);
        }

        // prime: lp for t=1 into buffer 1
        {
            float4 xv = xs[1];
            lps[64 + c0] = emis_ref(xv, mu0, sg0, lsg0);
            lps[64 + c1] = emis_ref(xv, mu1, sg1, lsg1);
        }
        asm volatile("bar.sync 1, 96;" ::: "memory");

        for (int t = 1; t < T; t++) {
            if (t + 1 < T) {
                float4 xq = xs[t + 1];
                float* dst = lps + ((t + 1) & 1) * 64;
                dst[c0] = emis_ref(xq, mu0, sg0, lsg0);
                dst[c1] = emis_ref(xq, mu1, sg1, lsg1);
            }
            asm volatile("bar.sync 1, 96;" ::: "memory");
        }

    } else {
        // ========== VITERBI (2 warps, 1 state/thread, ref-exact f32 ops) ==========
        const int c = tid - 64;
        const float pil = __fsub_rn(__fsub_rn(logpi[c], pimx), pils);

        float Al[64];
        #pragma unroll
        for (int j = 0; j < 64; j++)
            Al[j] = __fsub_rn(__fsub_rn(Abuf[j * 65 + c], rowmx[j]), rowls[j]);

        float* dprev = dbuf;
        float* dcur  = dbuf + 64;

        // t = 0: compute own emission once (params local to this scope only)
        {
            float mu[4], sg[4], lsg[4];
            #pragma unroll
            for (int d = 0; d < 4; d++) {
                sg[d]  = __fadd_rn(fmaxf(stds[c * 6 + d], 0.0f), 0.1f);
                mu[d]  = means[c * 6 + d];
                lsg[d] = logf(sg[d]);
            }
            float4 xv = xs[0];
            dprev[c] = __fadd_rn(emis_ref(xv, mu, sg, lsg), pil);
        }
        asm volatile("bar.sync 1, 96;" ::: "memory");

        for (int t = 1; t < T; t++) {
            float lp = lps[(t & 1) * 64 + c];   // produced by emission warp

            // 8 independent (best, argmax) chains over contiguous j-octets,
            // then a strict-'>' combine tree (left keeps ties) ==
            // first-max ascending scan == jnp.argmax semantics, bit-identical.
            float cb[8];
            int   ci[8];
            #pragma unroll
            for (int g = 0; g < 8; g++) {
                const int base = g * 8;
                float4 a0 = *(const float4*)(dprev + base);
                float4 a1 = *(const float4*)(dprev + base + 4);
                float bst = __fadd_rn(a0.x, Al[base]);
                int   idx = base;
                float v;
                v = __fadd_rn(a0.y, Al[base + 1]); if (v > bst) { bst = v; idx = base + 1; }
                v = __fadd_rn(a0.z, Al[base + 2]); if (v > bst) { bst = v; idx = base + 2; }
                v = __fadd_rn(a0.w, Al[base + 3]); if (v > bst) { bst = v; idx = base + 3; }
                v = __fadd_rn(a1.x, Al[base + 4]); if (v > bst) { bst = v; idx = base + 4; }
                v = __fadd_rn(a1.y, Al[base + 5]); if (v > bst) { bst = v; idx = base + 5; }
                v = __fadd_rn(a1.z, Al[base + 6]); if (v > bst) { bst = v; idx = base + 6; }
                v = __fadd_rn(a1.w, Al[base + 7]); if (v > bst) { bst = v; idx = base + 7; }
                cb[g] = bst; ci[g] = idx;
            }
            #pragma unroll
            for (int stp = 1; stp < 8; stp <<= 1)
                #pragma unroll
                for (int g = 0; g < 8; g += 2 * stp)
                    if (cb[g + stp] > cb[g]) { cb[g] = cb[g + stp]; ci[g] = ci[g + stp]; }

            dcur[c] = __fadd_rn(cb[0], lp);
            psi[(t - 1) * 64 + c] = (unsigned char)ci[0];
            asm volatile("bar.sync 1, 96;" ::: "memory");
            float* tmp = dprev; dprev = dcur; dcur = tmp;
        }

        // backtrack (single thread; psi in smem -> LDS-latency chase)
        if (c == 0) {
            float bb = dprev[0]; int cl = 0;
            #pragma unroll 8
            for (int j = 1; j < 64; j++) {
                float v = dprev[j];
                if (v > bb) { bb = v; cl = j; }
            }
            float* oc = out + HB + (size_t)b * T;
            int cc = cl;
            oc[T - 1] = (float)cc;
            for (int t = T - 2; t >= 0; --t) {
                cc = psi[t * 64 + cc];
                oc[t] = (float)cc;
            }
        }
    }
}

extern "C" void kernel_launch(void* const* d_in, const int* in_sizes, int n_in,
                              void* d_out, int out_size) {
    const float* x      = (const float*)d_in[0];
    const float* means  = (const float*)d_in[1];
    const float* stds   = (const float*)d_in[2];
    const float* logA   = (const float*)d_in[3];
    const float* logpi  = (const float*)d_in[4];
    float* out = (float*)d_out;

    int T = in_sizes[0] / (HB * 6);   // 2050

    size_t smem = 16 * (size_t)T          // xs
                + 128 * sizeof(float)     // abuf
                + 128 * sizeof(float)     // dbuf
                + 128 * sizeof(float)     // lps (emission dbl-buf)
                + 64 * 65 * sizeof(float) // Abuf (padded)
                + (64 + 64 + 16) * sizeof(float) // rowmx, rowls, piaux
                + (size_t)(T - 1) * 64;   // psi

    cudaFuncSetAttribute(MyHMM_14353780703777_kernel,
                         cudaFuncAttributeMaxDynamicSharedMemorySize, (int)smem);
    MyHMM_14353780703777_kernel<<<HB, 128, smem>>>(x, means, stds, logA, logpi, out, T);
}